// round 12
// baseline (speedup 1.0000x reference)
#include <cuda_runtime.h>
#include <cuda_bf16.h>
#include <math.h>
#include <stdint.h>

// Problem constants
#define BWIN 512      // windows
#define NTOK 64       // tokens per window
#define DIM  256
#define NH   8
#define HD   32

// Scratch (device globals; allocation-free per harness rules)
__device__ float g_q[2u*BWIN*NH*NTOK*HD];   // [view][win][h][n][d]  (normalized)
__device__ float g_k[2u*BWIN*NH*NTOK*HD];   // (normalized)
__device__ float g_v[2u*BWIN*NH*NTOK*HD];
__device__ float g_b16[2*NH*NTOK*NTOK];     // 16*sigmoid(cpb bias)

// bf16 hi/lo split pair arrays (pairs packed along K in one b32)
#define XPAIRS  (2u*32768u*128u)   // X: 8388608
#define WPAIRS  (2u*768u*128u)     // qkv W: 196608
#define PWPAIRS (2u*256u*128u)     // proj W: 65536
#define YPAIRS  (2u*32768u*128u)   // attn@V output Y
__device__ __align__(16) uint32_t g_xhi[XPAIRS];
__device__ __align__(16) uint32_t g_xlo[XPAIRS];
__device__ __align__(16) uint32_t g_whi[WPAIRS];
__device__ __align__(16) uint32_t g_wlo[WPAIRS];
__device__ __align__(16) uint32_t g_pwhi[PWPAIRS];
__device__ __align__(16) uint32_t g_pwlo[PWPAIRS];
__device__ __align__(16) uint32_t g_yhi[YPAIRS];
__device__ __align__(16) uint32_t g_ylo[YPAIRS];

// ---------------------------------------------------------------------------
// helpers
// ---------------------------------------------------------------------------
__device__ __forceinline__ void split_pair(float x0, float x1, uint32_t& hi, uint32_t& lo) {
    __nv_bfloat16 h0 = __float2bfloat16(x0);
    __nv_bfloat16 h1 = __float2bfloat16(x1);
    float r0 = x0 - __bfloat162float(h0);
    float r1 = x1 - __bfloat162float(h1);
    __nv_bfloat16 l0 = __float2bfloat16(r0);
    __nv_bfloat16 l1 = __float2bfloat16(r1);
    __nv_bfloat162 hp; hp.x = h0; hp.y = h1;
    __nv_bfloat162 lp; lp.x = l0; lp.y = l1;
    hi = *(uint32_t*)&hp;
    lo = *(uint32_t*)&lp;
}

__device__ __forceinline__ void mma_bf16(float* c, const uint32_t* a, const uint32_t* b) {
    asm volatile(
        "mma.sync.aligned.m16n8k16.row.col.f32.bf16.bf16.f32 "
        "{%0,%1,%2,%3}, {%4,%5,%6,%7}, {%8,%9}, {%0,%1,%2,%3};\n"
        : "+f"(c[0]), "+f"(c[1]), "+f"(c[2]), "+f"(c[3])
        : "r"(a[0]), "r"(a[1]), "r"(a[2]), "r"(a[3]), "r"(b[0]), "r"(b[1]));
}

// ---------------------------------------------------------------------------
// Kernel P: split X, qkv W, proj W into bf16 hi/lo pair arrays.
// ---------------------------------------------------------------------------
__global__ void prep_kernel(const float* __restrict__ x1, const float* __restrict__ x2,
                            const float* __restrict__ w1, const float* __restrict__ w2,
                            const float* __restrict__ pw1, const float* __restrict__ pw2)
{
    uint32_t idx = blockIdx.x * blockDim.x + threadIdx.x;
    if (idx < XPAIRS) {
        uint32_t view = idx >> 22;
        uint32_t off = idx & 0x3FFFFFu;
        const float2* src = (const float2*)(view ? x2 : x1);
        float2 v = src[off];
        uint32_t hi, lo;
        split_pair(v.x, v.y, hi, lo);
        g_xhi[idx] = hi; g_xlo[idx] = lo;
    } else if (idx < XPAIRS + WPAIRS) {
        uint32_t j = idx - XPAIRS;
        uint32_t view = j / 98304u;
        uint32_t off = j - view * 98304u;
        const float2* src = (const float2*)(view ? w2 : w1);
        float2 v = src[off];
        uint32_t hi, lo;
        split_pair(v.x, v.y, hi, lo);
        g_whi[j] = hi; g_wlo[j] = lo;
    } else if (idx < XPAIRS + WPAIRS + PWPAIRS) {
        uint32_t j = idx - XPAIRS - WPAIRS;
        uint32_t view = j >> 15;
        uint32_t off = j & 32767u;
        const float2* src = (const float2*)(view ? pw2 : pw1);
        float2 v = src[off];
        uint32_t hi, lo;
        split_pair(v.x, v.y, hi, lo);
        g_pwhi[j] = hi; g_pwlo[j] = lo;
    }
}

// ---------------------------------------------------------------------------
// Kernel 0: CPB MLP + gather + 16*sigmoid. One block per view.
// ---------------------------------------------------------------------------
__device__ __forceinline__ float cpb_coord(int i) {
    float x = 8.0f * (float)(i - 7) / 7.0f;
    float s = (x > 0.f) ? 1.f : ((x < 0.f) ? -1.f : 0.f);
    return s * log2f(fabsf(x) + 1.0f) * (1.0f / 3.0f);
}

__global__ void cpb_kernel(const float* __restrict__ w1a, const float* __restrict__ b1a,
                           const float* __restrict__ w2a,
                           const float* __restrict__ w1b, const float* __restrict__ b1b,
                           const float* __restrict__ w2b)
{
    int view = blockIdx.x;
    const float* W1 = view ? w1b : w1a;
    const float* B1 = view ? b1b : b1a;
    const float* W2 = view ? w2b : w2a;
    __shared__ float tbl[225][NH];
    int tid = threadIdx.x;
    if (tid < 225) {
        int a = tid / 15, b = tid % 15;
        float t0 = cpb_coord(a), t1 = cpb_coord(b);
        float o[NH];
#pragma unroll
        for (int h = 0; h < NH; h++) o[h] = 0.f;
        for (int j = 0; j < 512; j++) {
            float hid = t0 * W1[2*j] + t1 * W1[2*j+1] + B1[j];
            hid = fmaxf(hid, 0.f);
#pragma unroll
            for (int h = 0; h < NH; h++) o[h] += hid * W2[h*512 + j];
        }
#pragma unroll
        for (int h = 0; h < NH; h++) tbl[tid][h] = o[h];
    }
    __syncthreads();
    for (int idx = tid; idx < NH*NTOK*NTOK; idx += blockDim.x) {
        int h = idx >> 12;
        int n = (idx >> 6) & 63;
        int m = idx & 63;
        int i  = n >> 3, j  = n & 7;
        int i2 = m >> 3, j2 = m & 7;
        int e = (i - i2 + 7) * 15 + (j - j2 + 7);
        float bb = tbl[e][h];
        g_b16[view*NH*NTOK*NTOK + idx] = 16.0f / (1.0f + expf(-bb));
    }
}

// ---------------------------------------------------------------------------
// Kernel 1: QKV GEMM via mma.sync bf16 (2-term split). (proven in R2)
// ---------------------------------------------------------------------------
#define QSM_BYTES 33280

__global__ void __launch_bounds__(256, 1) qkv_mma_kernel(
    const float* __restrict__ qb1, const float* __restrict__ vb1,
    const float* __restrict__ qb2, const float* __restrict__ vb2)
{
    extern __shared__ uint32_t smu[];
    uint32_t* sA_hi = smu;           // [128][20]
    uint32_t* sA_lo = smu + 2560;
    uint32_t* sB_hi = smu + 5120;    // [64][20]
    uint32_t* sB_lo = smu + 6400;

    int tid = threadIdx.x;
    int wid = tid >> 5, lane = tid & 31;
    int warp_m = wid & 3, warp_n = wid >> 2;
    int nt = blockIdx.x;      // 0..11
    int mt = blockIdx.y;      // 0..255
    int view = blockIdx.z;

    const float* QB = view ? qb2 : qb1;
    const float* VB = view ? vb2 : vb1;

    float c[2][4][4];
#pragma unroll
    for (int i = 0; i < 2; i++)
#pragma unroll
        for (int j = 0; j < 4; j++)
#pragma unroll
            for (int r = 0; r < 4; r++) c[i][j][r] = 0.f;

    uint32_t arow0 = (uint32_t)(view*32768 + mt*128);
    uint32_t brow0 = (uint32_t)(view*768 + nt*64);

    int lg = lane >> 2;
    int lc = lane & 3;

    for (int kc = 0; kc < 8; kc++) {
        __syncthreads();
#pragma unroll
        for (int t = 0; t < 2; t++) {
            int idx = t*256 + tid;
            int row = idx >> 2, cc = (idx & 3) * 4;
            uint32_t gofs = (arow0 + row)*128u + kc*16 + cc;
            *(uint4*)(sA_hi + row*20 + cc) = *(const uint4*)(g_xhi + gofs);
            *(uint4*)(sA_lo + row*20 + cc) = *(const uint4*)(g_xlo + gofs);
        }
        {
            int row = tid >> 2, cc = (tid & 3) * 4;
            uint32_t gofs = (brow0 + row)*128u + kc*16 + cc;
            *(uint4*)(sB_hi + row*20 + cc) = *(const uint4*)(g_whi + gofs);
            *(uint4*)(sB_lo + row*20 + cc) = *(const uint4*)(g_wlo + gofs);
        }
        __syncthreads();

#pragma unroll
        for (int ks = 0; ks < 2; ks++) {
            uint32_t ah[2][4], al[2][4], bh[4][2], bl[4][2];
#pragma unroll
            for (int i = 0; i < 2; i++) {
                int r0 = warp_m*32 + 16*i + lg;
                int kb = ks*8 + lc;
                ah[i][0] = sA_hi[r0*20 + kb];
                ah[i][1] = sA_hi[(r0+8)*20 + kb];
                ah[i][2] = sA_hi[r0*20 + kb + 4];
                ah[i][3] = sA_hi[(r0+8)*20 + kb + 4];
                al[i][0] = sA_lo[r0*20 + kb];
                al[i][1] = sA_lo[(r0+8)*20 + kb];
                al[i][2] = sA_lo[r0*20 + kb + 4];
                al[i][3] = sA_lo[(r0+8)*20 + kb + 4];
            }
#pragma unroll
            for (int j = 0; j < 4; j++) {
                int n = warp_n*32 + 8*j + lg;
                int kb = ks*8 + lc;
                bh[j][0] = sB_hi[n*20 + kb];
                bh[j][1] = sB_hi[n*20 + kb + 4];
                bl[j][0] = sB_lo[n*20 + kb];
                bl[j][1] = sB_lo[n*20 + kb + 4];
            }
#pragma unroll
            for (int i = 0; i < 2; i++)
#pragma unroll
                for (int j = 0; j < 4; j++) {
                    mma_bf16(c[i][j], ah[i], bh[j]);
                    mma_bf16(c[i][j], ah[i], bl[j]);
                    mma_bf16(c[i][j], al[i], bh[j]);
                }
        }
    }
    __syncthreads();

    float* s_out = (float*)smu;
#pragma unroll
    for (int i = 0; i < 2; i++) {
        int row = warp_m*32 + 16*i + lg;
#pragma unroll
        for (int j = 0; j < 4; j++) {
            int col = warp_n*32 + 8*j + lc*2;
            s_out[row*65 + col]     = c[i][j][0];
            s_out[row*65 + col + 1] = c[i][j][1];
            s_out[(row+8)*65 + col]     = c[i][j][2];
            s_out[(row+8)*65 + col + 1] = c[i][j][3];
        }
    }
    __syncthreads();

    {
        int m = tid >> 1, g = tid & 1;
        int cbase = nt*64 + g*32;
        int s = cbase >> 8;
        int hc = cbase & 255;
        int h = hc >> 5;
        float vals[32];
#pragma unroll
        for (int d = 0; d < 32; d++) vals[d] = s_out[m*65 + g*32 + d];
        if (s == 0) {
#pragma unroll
            for (int d = 0; d < 32; d++) vals[d] += QB[hc + d];
        } else if (s == 2) {
#pragma unroll
            for (int d = 0; d < 32; d++) vals[d] += VB[hc + d];
        }
        if (s <= 1) {
            float ss = 0.f;
#pragma unroll
            for (int d = 0; d < 32; d++) ss += vals[d] * vals[d];
            float inv = 1.0f / fmaxf(sqrtf(ss), 1e-12f);
#pragma unroll
            for (int d = 0; d < 32; d++) vals[d] *= inv;
        }
        int grow = mt*128 + m;
        int win = grow >> 6, ntok = grow & 63;
        size_t idx = ((((size_t)(view*BWIN + win))*NH + h)*NTOK + ntok)*HD;
        float* dst = (s == 0) ? g_q : ((s == 1) ? g_k : g_v);
#pragma unroll
        for (int d4 = 0; d4 < 8; d4++)
            *(float4*)(dst + idx + d4*4) = *(float4*)(vals + d4*4);
    }
}

// ---------------------------------------------------------------------------
// Kernel 2: attention via mma. One block per (win, view), 512 threads.
// Scores (bf16 split mma, staged per head-pair) -> SIMT head mix -> softmax
// -> attn@V (mma) -> Y written as bf16 pair split to global for proj kernel.
// ---------------------------------------------------------------------------
// smem word-offset map
#define AT_RB    33792                 // s_attn = [512][66] fp32 before this
#define AT_QHI   (AT_RB)               // [64][20] b32 each
#define AT_QLO   (AT_RB+1280)
#define AT_KSHI  (AT_RB+2560)
#define AT_KSLO  (AT_RB+3840)
#define AT_KDHI  (AT_RB+5120)
#define AT_KDLO  (AT_RB+6400)
#define AT_SSAME (AT_RB+7680)          // [64][72] fp32
#define AT_SDIFF (AT_RB+12288)
#define AT_VTHI  (AT_RB)               // [8][32][37] b32 (overlays tiles+S)
#define AT_VTLO  (AT_RB+9472)
#define AT_SMALL (AT_RB+18944)         // pcw 128 | pcb 8 | scale 8
#define AT_WORDS (AT_SMALL+144)
#define AT_BYTES (AT_WORDS*4)

__global__ void __launch_bounds__(512, 1) attn2_kernel(
    const float* __restrict__ ls1, const float* __restrict__ pcw1, const float* __restrict__ pcb1,
    const float* __restrict__ ls2, const float* __restrict__ pcw2, const float* __restrict__ pcb2)
{
    extern __shared__ float smf[];
    uint32_t* smu = (uint32_t*)smf;
    int win = blockIdx.x, view = blockIdx.y;
    const float* LS  = view ? ls2  : ls1;
    const float* PCW = view ? pcw2 : pcw1;
    const float* PCB = view ? pcb2 : pcb1;
    int tid = threadIdx.x, wid = tid >> 5, lane = tid & 31;

    float* s_pcw   = smf + AT_SMALL;
    float* s_pcb   = smf + AT_SMALL + 128;
    float* s_scale = smf + AT_SMALL + 136;
    if (tid < 128) s_pcw[tid] = PCW[tid];
    if (tid < 8) {
        s_pcb[tid] = PCB[tid];
        s_scale[tid] = expf(fminf(LS[tid], 4.605170186f));
    }

    size_t base_same = ((size_t)(view*BWIN + win)) * NH * NTOK * HD;
    size_t base_diff = ((size_t)((view^1)*BWIN + win)) * NH * NTOK * HD;

    int m = tid & 63, nb = tid >> 6;
    float acc[8][8];
#pragma unroll
    for (int i = 0; i < 8; i++)
#pragma unroll
        for (int h = 0; h < 8; h++) acc[i][h] = 0.f;

    // score warp roles: sd (same/diff), mt (16-row n tile), nh (32-col m half)
    int sdw = wid & 1, mt = (wid >> 1) & 3, nhh = wid >> 3;
    int lg = lane >> 2, lc = lane & 3;

    for (int hp = 0; hp < 8; hp++) {
        __syncthreads();
        // stage q / k_same / k_diff tiles as bf16 hi/lo pairs [64][20]
#pragma unroll
        for (int t = 0; t < 6; t++) {
            int idx = t*512 + tid;              // 0..3071
            int tensor = idx >> 10;
            int p = idx & 1023;
            int r = p >> 4, dp = p & 15;
            const float* src = (tensor == 0) ? (g_q + base_same)
                              : ((tensor == 1) ? (g_k + base_same) : (g_k + base_diff));
            float2 v = *(const float2*)(src + hp*2048 + r*32 + dp*2);
            uint32_t hi, lo;
            split_pair(v.x, v.y, hi, lo);
            int bofs = AT_RB + tensor*2560;
            smu[bofs + r*20 + dp] = hi;
            smu[bofs + 1280 + r*20 + dp] = lo;
        }
        __syncthreads();

        // mma: C[16 n][32 m] per warp
        {
            uint32_t* qhi = smu + AT_QHI;
            uint32_t* qlo = smu + AT_QLO;
            uint32_t* khi = smu + (sdw ? AT_KDHI : AT_KSHI);
            uint32_t* klo = smu + (sdw ? AT_KDLO : AT_KSLO);
            float c[4][4];
#pragma unroll
            for (int j = 0; j < 4; j++)
#pragma unroll
                for (int r = 0; r < 4; r++) c[j][r] = 0.f;

#pragma unroll
            for (int ks = 0; ks < 2; ks++) {
                int kb = ks*8 + lc;
                int r0 = mt*16 + lg;
                uint32_t ah[4], al[4];
                ah[0] = qhi[r0*20 + kb];       ah[1] = qhi[(r0+8)*20 + kb];
                ah[2] = qhi[r0*20 + kb + 4];   ah[3] = qhi[(r0+8)*20 + kb + 4];
                al[0] = qlo[r0*20 + kb];       al[1] = qlo[(r0+8)*20 + kb];
                al[2] = qlo[r0*20 + kb + 4];   al[3] = qlo[(r0+8)*20 + kb + 4];
#pragma unroll
                for (int j = 0; j < 4; j++) {
                    int mm = nhh*32 + j*8 + lg;
                    uint32_t bh[2], bl[2];
                    bh[0] = khi[mm*20 + kb]; bh[1] = khi[mm*20 + kb + 4];
                    bl[0] = klo[mm*20 + kb]; bl[1] = klo[mm*20 + kb + 4];
                    mma_bf16(c[j], ah, bh);
                    mma_bf16(c[j], ah, bl);
                    mma_bf16(c[j], al, bh);
                }
            }
            // STS to s_same / s_diff [64][72]
            float* sS = smf + (sdw ? AT_SDIFF : AT_SSAME);
            int r0 = mt*16 + lg;
#pragma unroll
            for (int j = 0; j < 4; j++) {
                int col = nhh*32 + j*8 + lc*2;
                sS[r0*72 + col]       = c[j][0];
                sS[r0*72 + col + 1]   = c[j][1];
                sS[(r0+8)*72 + col]     = c[j][2];
                sS[(r0+8)*72 + col + 1] = c[j][3];
            }
        }
        __syncthreads();

        // SIMT head mix: acc[i][h] += w_same[h,hp]*S_same + w_diff[h,hp]*S_diff
#pragma unroll
        for (int i = 0; i < 8; i++) {
            float ssv = smf[AT_SSAME + (nb + 8*i)*72 + m];
            float sdv = smf[AT_SDIFF + (nb + 8*i)*72 + m];
#pragma unroll
            for (int h = 0; h < 8; h++)
                acc[i][h] += s_pcw[h*16 + hp]*ssv + s_pcw[h*16 + 8 + hp]*sdv;
        }
    }

    // logits -> s_attn [512][66]
    const float* gb = g_b16 + view * NH * NTOK * NTOK;
#pragma unroll
    for (int i = 0; i < 8; i++) {
        int n = nb + 8*i;
#pragma unroll
        for (int h = 0; h < 8; h++) {
            float logit = (acc[i][h] + s_pcb[h]) * s_scale[h] + gb[(h*64 + n)*64 + m];
            smf[(h*64 + n)*66 + m] = logit;
        }
    }
    __syncthreads();

    // softmax: warp per row
    for (int r = wid; r < 512; r += 16) {
        float* row = smf + r*66;
        float a = row[lane], b = row[lane + 32];
        float mx = fmaxf(a, b);
#pragma unroll
        for (int off = 16; off > 0; off >>= 1) mx = fmaxf(mx, __shfl_xor_sync(0xffffffffu, mx, off));
        float e1 = expf(a - mx), e2 = expf(b - mx);
        float s = e1 + e2;
#pragma unroll
        for (int off = 16; off > 0; off >>= 1) s += __shfl_xor_sync(0xffffffffu, s, off);
        float inv = 1.0f / s;
        row[lane] = e1 * inv;
        row[lane + 32] = e2 * inv;
    }
    __syncthreads();

    // stage V transposed bf16 pairs: vt[h][d 0..31][mpair 0..31] stride 37
#pragma unroll
    for (int t = 0; t < 4; t++) {
        int idx = t*512 + tid;               // (h, mp, dg)
        int h = idx >> 8, mp = (idx >> 3) & 31, dg = idx & 7;
        const float* vb = g_v + base_same + h*2048;
        float4 v0 = *(const float4*)(vb + (2*mp)*32 + dg*4);
        float4 v1 = *(const float4*)(vb + (2*mp + 1)*32 + dg*4);
        const float* p0 = (const float*)&v0;
        const float* p1 = (const float*)&v1;
#pragma unroll
        for (int u = 0; u < 4; u++) {
            uint32_t hi, lo;
            split_pair(p0[u], p1[u], hi, lo);
            int d = dg*4 + u;
            smu[AT_VTHI + h*1184 + d*37 + mp] = hi;
            smu[AT_VTLO + h*1184 + d*37 + mp] = lo;
        }
    }
    __syncthreads();

    // attn@V: warp = (head, 32-row n tile). C[32 n][32 d] per warp.
    {
        int h = wid >> 1, nt2 = wid & 1;
        float c2[2][4][4];
#pragma unroll
        for (int i = 0; i < 2; i++)
#pragma unroll
            for (int j = 0; j < 4; j++)
#pragma unroll
                for (int r = 0; r < 4; r++) c2[i][j][r] = 0.f;

        const float* srow = smf + (h*64 + nt2*32)*66;
#pragma unroll
        for (int kc = 0; kc < 4; kc++) {
            uint32_t ah[2][4], al[2][4];
#pragma unroll
            for (int i = 0; i < 2; i++) {
                int r = i*16 + lg;
                int k = kc*16 + lc*2;
#pragma unroll
                for (int u = 0; u < 4; u++) {
                    int rr = r + (u & 1)*8;
                    int kk = k + (u >> 1)*8;
                    float x0 = srow[rr*66 + kk];
                    float x1 = srow[rr*66 + kk + 1];
                    split_pair(x0, x1, ah[i][u], al[i][u]);
                }
            }
#pragma unroll
            for (int j = 0; j < 4; j++) {
                int d = j*8 + lg;
                int mpb = kc*8 + lc;
                uint32_t bh[2], bl[2];
                bh[0] = smu[AT_VTHI + h*1184 + d*37 + mpb];
                bh[1] = smu[AT_VTHI + h*1184 + d*37 + mpb + 4];
                bl[0] = smu[AT_VTLO + h*1184 + d*37 + mpb];
                bl[1] = smu[AT_VTLO + h*1184 + d*37 + mpb + 4];
#pragma unroll
                for (int i = 0; i < 2; i++) {
                    mma_bf16(c2[i][j], ah[i], bh);
                    mma_bf16(c2[i][j], ah[i], bl);
                    mma_bf16(c2[i][j], al[i], bh);
                }
            }
        }

        // write Y as bf16 pair split to global (pairs along channel)
        uint32_t yrow0 = ((uint32_t)(view*BWIN + win))*64u;
#pragma unroll
        for (int i = 0; i < 2; i++) {
            int n0 = nt2*32 + i*16 + lg;
#pragma unroll
            for (int j = 0; j < 4; j++) {
                int pidx = h*16 + j*4 + lc;
                uint32_t hi, lo;
                split_pair(c2[i][j][0], c2[i][j][1], hi, lo);
                g_yhi[(yrow0 + n0)*128u + pidx] = hi;
                g_ylo[(yrow0 + n0)*128u + pidx] = lo;
                split_pair(c2[i][j][2], c2[i][j][3], hi, lo);
                g_yhi[(yrow0 + n0 + 8)*128u + pidx] = hi;
                g_ylo[(yrow0 + n0 + 8)*128u + pidx] = lo;
            }
        }
    }
}

// ---------------------------------------------------------------------------
// Kernel 3: proj GEMM: out = Y @ PW^T + PB. Clone of qkv_mma structure.
// ---------------------------------------------------------------------------
__global__ void __launch_bounds__(256, 1) proj_mma_kernel(
    const float* __restrict__ pb1, const float* __restrict__ pb2,
    float* __restrict__ out)
{
    extern __shared__ uint32_t smu[];
    uint32_t* sA_hi = smu;           // [128][20]
    uint32_t* sA_lo = smu + 2560;
    uint32_t* sB_hi = smu + 5120;    // [64][20]
    uint32_t* sB_lo = smu + 6400;

    int tid = threadIdx.x;
    int wid = tid >> 5, lane = tid & 31;
    int warp_m = wid & 3, warp_n = wid >> 2;
    int nt = blockIdx.x;      // 0..3
    int mt = blockIdx.y;      // 0..255
    int view = blockIdx.z;

    const float* PB = view ? pb2 : pb1;

    float c[2][4][4];
#pragma unroll
    for (int i = 0; i < 2; i++)
#pragma unroll
        for (int j = 0; j < 4; j++)
#pragma unroll
            for (int r = 0; r < 4; r++) c[i][j][r] = 0.f;

    uint32_t arow0 = (uint32_t)(view*32768 + mt*128);
    uint32_t brow0 = (uint32_t)(view*256 + nt*64);

    int lg = lane >> 2;
    int lc = lane & 3;

    for (int kc = 0; kc < 8; kc++) {
        __syncthreads();
#pragma unroll
        for (int t = 0; t < 2; t++) {
            int idx = t*256 + tid;
            int row = idx >> 2, cc = (idx & 3) * 4;
            uint32_t gofs = (arow0 + row)*128u + kc*16 + cc;
            *(uint4*)(sA_hi + row*20 + cc) = *(const uint4*)(g_yhi + gofs);
            *(uint4*)(sA_lo + row*20 + cc) = *(const uint4*)(g_ylo + gofs);
        }
        {
            int row = tid >> 2, cc = (tid & 3) * 4;
            uint32_t gofs = (brow0 + row)*128u + kc*16 + cc;
            *(uint4*)(sB_hi + row*20 + cc) = *(const uint4*)(g_pwhi + gofs);
            *(uint4*)(sB_lo + row*20 + cc) = *(const uint4*)(g_pwlo + gofs);
        }
        __syncthreads();

#pragma unroll
        for (int ks = 0; ks < 2; ks++) {
            uint32_t ah[2][4], al[2][4], bh[4][2], bl[4][2];
#pragma unroll
            for (int i = 0; i < 2; i++) {
                int r0 = warp_m*32 + 16*i + lg;
                int kb = ks*8 + lc;
                ah[i][0] = sA_hi[r0*20 + kb];
                ah[i][1] = sA_hi[(r0+8)*20 + kb];
                ah[i][2] = sA_hi[r0*20 + kb + 4];
                ah[i][3] = sA_hi[(r0+8)*20 + kb + 4];
                al[i][0] = sA_lo[r0*20 + kb];
                al[i][1] = sA_lo[(r0+8)*20 + kb];
                al[i][2] = sA_lo[r0*20 + kb + 4];
                al[i][3] = sA_lo[(r0+8)*20 + kb + 4];
            }
#pragma unroll
            for (int j = 0; j < 4; j++) {
                int n = warp_n*32 + 8*j + lg;
                int kb = ks*8 + lc;
                bh[j][0] = sB_hi[n*20 + kb];
                bh[j][1] = sB_hi[n*20 + kb + 4];
                bl[j][0] = sB_lo[n*20 + kb];
                bl[j][1] = sB_lo[n*20 + kb + 4];
            }
#pragma unroll
            for (int i = 0; i < 2; i++)
#pragma unroll
                for (int j = 0; j < 4; j++) {
                    mma_bf16(c[i][j], ah[i], bh[j]);
                    mma_bf16(c[i][j], ah[i], bl[j]);
                    mma_bf16(c[i][j], al[i], bh[j]);
                }
        }
    }
    __syncthreads();

    float* s_out = (float*)smu;
#pragma unroll
    for (int i = 0; i < 2; i++) {
        int row = warp_m*32 + 16*i + lg;
#pragma unroll
        for (int j = 0; j < 4; j++) {
            int col = warp_n*32 + 8*j + lc*2;
            s_out[row*65 + col]     = c[i][j][0];
            s_out[row*65 + col + 1] = c[i][j][1];
            s_out[(row+8)*65 + col]     = c[i][j][2];
            s_out[(row+8)*65 + col + 1] = c[i][j][3];
        }
    }
    __syncthreads();

    for (int i = tid; i < 8192; i += 256) {
        int mm = i >> 6, j = i & 63;
        int grow = mt*128 + mm;
        out[((size_t)view*32768 + grow)*256 + nt*64 + j] = s_out[mm*65 + j] + PB[nt*64 + j];
    }
}

// ---------------------------------------------------------------------------
extern "C" void kernel_launch(void* const* d_in, const int* in_sizes, int n_in,
                              void* d_out, int out_size)
{
    const float* x1   = (const float*)d_in[0];
    const float* x2   = (const float*)d_in[1];
    const float* qkvw1 = (const float*)d_in[2];
    const float* qb1  = (const float*)d_in[3];
    const float* vb1  = (const float*)d_in[4];
    const float* pw1  = (const float*)d_in[5];
    const float* pb1  = (const float*)d_in[6];
    const float* ls1  = (const float*)d_in[7];
    const float* c1w1 = (const float*)d_in[8];
    const float* c1b1 = (const float*)d_in[9];
    const float* c1w2 = (const float*)d_in[10];
    const float* pcw1 = (const float*)d_in[11];
    const float* pcb1 = (const float*)d_in[12];
    const float* qkvw2 = (const float*)d_in[13];
    const float* qb2  = (const float*)d_in[14];
    const float* vb2  = (const float*)d_in[15];
    const float* pw2  = (const float*)d_in[16];
    const float* pb2  = (const float*)d_in[17];
    const float* ls2  = (const float*)d_in[18];
    const float* c2w1 = (const float*)d_in[19];
    const float* c2b1 = (const float*)d_in[20];
    const float* c2w2 = (const float*)d_in[21];
    const float* pcw2 = (const float*)d_in[22];
    const float* pcb2 = (const float*)d_in[23];
    float* out = (float*)d_out;

    cpb_kernel<<<2, 256>>>(c1w1, c1b1, c1w2, c2w1, c2b1, c2w2);

    {
        uint32_t total = XPAIRS + WPAIRS + PWPAIRS;
        prep_kernel<<<(total + 255) / 256, 256>>>(x1, x2, qkvw1, qkvw2, pw1, pw2);
    }

    cudaFuncSetAttribute(qkv_mma_kernel, cudaFuncAttributeMaxDynamicSharedMemorySize, QSM_BYTES);
    qkv_mma_kernel<<<dim3(12, 256, 2), 256, QSM_BYTES>>>(qb1, vb1, qb2, vb2);

    cudaFuncSetAttribute(attn2_kernel, cudaFuncAttributeMaxDynamicSharedMemorySize, AT_BYTES);
    attn2_kernel<<<dim3(512, 2), 512, AT_BYTES>>>(ls1, pcw1, pcb1, ls2, pcw2, pcb2);

    cudaFuncSetAttribute(proj_mma_kernel, cudaFuncAttributeMaxDynamicSharedMemorySize, QSM_BYTES);
    proj_mma_kernel<<<dim3(4, 256, 2), 256, QSM_BYTES>>>(pb1, pb2, out);
}

// round 13
// speedup vs baseline: 1.0028x; 1.0028x over previous
#include <cuda_runtime.h>
#include <cuda_bf16.h>
#include <math.h>
#include <stdint.h>

// Problem constants
#define BWIN 512      // windows
#define NTOK 64       // tokens per window
#define DIM  256
#define NH   8
#define HD   32

// Scratch (device globals; allocation-free per harness rules)
__device__ float g_q[2u*BWIN*NH*NTOK*HD];   // [view][win][h][n][d]  (normalized)
__device__ float g_k[2u*BWIN*NH*NTOK*HD];   // (normalized)
__device__ float g_v[2u*BWIN*NH*NTOK*HD];
__device__ float g_b16[2*NH*NTOK*NTOK];     // 16*sigmoid(cpb bias)

// bf16 hi/lo split pair arrays (pairs packed along K in one b32)
#define XPAIRS  (2u*32768u*128u)   // X: 8388608
#define WPAIRS  (2u*768u*128u)     // qkv W: 196608
#define PWPAIRS (2u*256u*128u)     // proj W: 65536
#define YPAIRS  (2u*32768u*128u)   // attn@V output Y
__device__ __align__(16) uint32_t g_xhi[XPAIRS];
__device__ __align__(16) uint32_t g_xlo[XPAIRS];
__device__ __align__(16) uint32_t g_whi[WPAIRS];
__device__ __align__(16) uint32_t g_wlo[WPAIRS];
__device__ __align__(16) uint32_t g_pwhi[PWPAIRS];
__device__ __align__(16) uint32_t g_pwlo[PWPAIRS];
__device__ __align__(16) uint32_t g_yhi[YPAIRS];
__device__ __align__(16) uint32_t g_ylo[YPAIRS];

// ---------------------------------------------------------------------------
// helpers
// ---------------------------------------------------------------------------
__device__ __forceinline__ void split_pair(float x0, float x1, uint32_t& hi, uint32_t& lo) {
    __nv_bfloat16 h0 = __float2bfloat16(x0);
    __nv_bfloat16 h1 = __float2bfloat16(x1);
    float r0 = x0 - __bfloat162float(h0);
    float r1 = x1 - __bfloat162float(h1);
    __nv_bfloat16 l0 = __float2bfloat16(r0);
    __nv_bfloat16 l1 = __float2bfloat16(r1);
    __nv_bfloat162 hp; hp.x = h0; hp.y = h1;
    __nv_bfloat162 lp; lp.x = l0; lp.y = l1;
    hi = *(uint32_t*)&hp;
    lo = *(uint32_t*)&lp;
}

__device__ __forceinline__ void mma_bf16(float* c, const uint32_t* a, const uint32_t* b) {
    asm volatile(
        "mma.sync.aligned.m16n8k16.row.col.f32.bf16.bf16.f32 "
        "{%0,%1,%2,%3}, {%4,%5,%6,%7}, {%8,%9}, {%0,%1,%2,%3};\n"
        : "+f"(c[0]), "+f"(c[1]), "+f"(c[2]), "+f"(c[3])
        : "r"(a[0]), "r"(a[1]), "r"(a[2]), "r"(a[3]), "r"(b[0]), "r"(b[1]));
}

// ---------------------------------------------------------------------------
// Kernel P: split X, qkv W, proj W into bf16 hi/lo pair arrays.
// ---------------------------------------------------------------------------
__global__ void prep_kernel(const float* __restrict__ x1, const float* __restrict__ x2,
                            const float* __restrict__ w1, const float* __restrict__ w2,
                            const float* __restrict__ pw1, const float* __restrict__ pw2)
{
    uint32_t idx = blockIdx.x * blockDim.x + threadIdx.x;
    if (idx < XPAIRS) {
        uint32_t view = idx >> 22;
        uint32_t off = idx & 0x3FFFFFu;
        const float2* src = (const float2*)(view ? x2 : x1);
        float2 v = src[off];
        uint32_t hi, lo;
        split_pair(v.x, v.y, hi, lo);
        g_xhi[idx] = hi; g_xlo[idx] = lo;
    } else if (idx < XPAIRS + WPAIRS) {
        uint32_t j = idx - XPAIRS;
        uint32_t view = j / 98304u;
        uint32_t off = j - view * 98304u;
        const float2* src = (const float2*)(view ? w2 : w1);
        float2 v = src[off];
        uint32_t hi, lo;
        split_pair(v.x, v.y, hi, lo);
        g_whi[j] = hi; g_wlo[j] = lo;
    } else if (idx < XPAIRS + WPAIRS + PWPAIRS) {
        uint32_t j = idx - XPAIRS - WPAIRS;
        uint32_t view = j >> 15;
        uint32_t off = j & 32767u;
        const float2* src = (const float2*)(view ? pw2 : pw1);
        float2 v = src[off];
        uint32_t hi, lo;
        split_pair(v.x, v.y, hi, lo);
        g_pwhi[j] = hi; g_pwlo[j] = lo;
    }
}

// ---------------------------------------------------------------------------
// Kernel 0: CPB MLP + gather + 16*sigmoid. One block per view.
// ---------------------------------------------------------------------------
__device__ __forceinline__ float cpb_coord(int i) {
    float x = 8.0f * (float)(i - 7) / 7.0f;
    float s = (x > 0.f) ? 1.f : ((x < 0.f) ? -1.f : 0.f);
    return s * log2f(fabsf(x) + 1.0f) * (1.0f / 3.0f);
}

__global__ void cpb_kernel(const float* __restrict__ w1a, const float* __restrict__ b1a,
                           const float* __restrict__ w2a,
                           const float* __restrict__ w1b, const float* __restrict__ b1b,
                           const float* __restrict__ w2b)
{
    int view = blockIdx.x;
    const float* W1 = view ? w1b : w1a;
    const float* B1 = view ? b1b : b1a;
    const float* W2 = view ? w2b : w2a;
    __shared__ float tbl[225][NH];
    int tid = threadIdx.x;
    if (tid < 225) {
        int a = tid / 15, b = tid % 15;
        float t0 = cpb_coord(a), t1 = cpb_coord(b);
        float o[NH];
#pragma unroll
        for (int h = 0; h < NH; h++) o[h] = 0.f;
        for (int j = 0; j < 512; j++) {
            float hid = t0 * W1[2*j] + t1 * W1[2*j+1] + B1[j];
            hid = fmaxf(hid, 0.f);
#pragma unroll
            for (int h = 0; h < NH; h++) o[h] += hid * W2[h*512 + j];
        }
#pragma unroll
        for (int h = 0; h < NH; h++) tbl[tid][h] = o[h];
    }
    __syncthreads();
    for (int idx = tid; idx < NH*NTOK*NTOK; idx += blockDim.x) {
        int h = idx >> 12;
        int n = (idx >> 6) & 63;
        int m = idx & 63;
        int i  = n >> 3, j  = n & 7;
        int i2 = m >> 3, j2 = m & 7;
        int e = (i - i2 + 7) * 15 + (j - j2 + 7);
        float bb = tbl[e][h];
        g_b16[view*NH*NTOK*NTOK + idx] = 16.0f / (1.0f + expf(-bb));
    }
}

// ---------------------------------------------------------------------------
// Kernel 1: QKV GEMM via mma.sync bf16 (2-term split). (proven in R2)
// ---------------------------------------------------------------------------
#define QSM_BYTES 33280

__global__ void __launch_bounds__(256, 1) qkv_mma_kernel(
    const float* __restrict__ qb1, const float* __restrict__ vb1,
    const float* __restrict__ qb2, const float* __restrict__ vb2)
{
    extern __shared__ uint32_t smu[];
    uint32_t* sA_hi = smu;           // [128][20]
    uint32_t* sA_lo = smu + 2560;
    uint32_t* sB_hi = smu + 5120;    // [64][20]
    uint32_t* sB_lo = smu + 6400;

    int tid = threadIdx.x;
    int wid = tid >> 5, lane = tid & 31;
    int warp_m = wid & 3, warp_n = wid >> 2;
    int nt = blockIdx.x;      // 0..11
    int mt = blockIdx.y;      // 0..255
    int view = blockIdx.z;

    const float* QB = view ? qb2 : qb1;
    const float* VB = view ? vb2 : vb1;

    float c[2][4][4];
#pragma unroll
    for (int i = 0; i < 2; i++)
#pragma unroll
        for (int j = 0; j < 4; j++)
#pragma unroll
            for (int r = 0; r < 4; r++) c[i][j][r] = 0.f;

    uint32_t arow0 = (uint32_t)(view*32768 + mt*128);
    uint32_t brow0 = (uint32_t)(view*768 + nt*64);

    int lg = lane >> 2;
    int lc = lane & 3;

    for (int kc = 0; kc < 8; kc++) {
        __syncthreads();
#pragma unroll
        for (int t = 0; t < 2; t++) {
            int idx = t*256 + tid;
            int row = idx >> 2, cc = (idx & 3) * 4;
            uint32_t gofs = (arow0 + row)*128u + kc*16 + cc;
            *(uint4*)(sA_hi + row*20 + cc) = *(const uint4*)(g_xhi + gofs);
            *(uint4*)(sA_lo + row*20 + cc) = *(const uint4*)(g_xlo + gofs);
        }
        {
            int row = tid >> 2, cc = (tid & 3) * 4;
            uint32_t gofs = (brow0 + row)*128u + kc*16 + cc;
            *(uint4*)(sB_hi + row*20 + cc) = *(const uint4*)(g_whi + gofs);
            *(uint4*)(sB_lo + row*20 + cc) = *(const uint4*)(g_wlo + gofs);
        }
        __syncthreads();

#pragma unroll
        for (int ks = 0; ks < 2; ks++) {
            uint32_t ah[2][4], al[2][4], bh[4][2], bl[4][2];
#pragma unroll
            for (int i = 0; i < 2; i++) {
                int r0 = warp_m*32 + 16*i + lg;
                int kb = ks*8 + lc;
                ah[i][0] = sA_hi[r0*20 + kb];
                ah[i][1] = sA_hi[(r0+8)*20 + kb];
                ah[i][2] = sA_hi[r0*20 + kb + 4];
                ah[i][3] = sA_hi[(r0+8)*20 + kb + 4];
                al[i][0] = sA_lo[r0*20 + kb];
                al[i][1] = sA_lo[(r0+8)*20 + kb];
                al[i][2] = sA_lo[r0*20 + kb + 4];
                al[i][3] = sA_lo[(r0+8)*20 + kb + 4];
            }
#pragma unroll
            for (int j = 0; j < 4; j++) {
                int n = warp_n*32 + 8*j + lg;
                int kb = ks*8 + lc;
                bh[j][0] = sB_hi[n*20 + kb];
                bh[j][1] = sB_hi[n*20 + kb + 4];
                bl[j][0] = sB_lo[n*20 + kb];
                bl[j][1] = sB_lo[n*20 + kb + 4];
            }
#pragma unroll
            for (int i = 0; i < 2; i++)
#pragma unroll
                for (int j = 0; j < 4; j++) {
                    mma_bf16(c[i][j], ah[i], bh[j]);
                    mma_bf16(c[i][j], ah[i], bl[j]);
                    mma_bf16(c[i][j], al[i], bh[j]);
                }
        }
    }
    __syncthreads();

    float* s_out = (float*)smu;
#pragma unroll
    for (int i = 0; i < 2; i++) {
        int row = warp_m*32 + 16*i + lg;
#pragma unroll
        for (int j = 0; j < 4; j++) {
            int col = warp_n*32 + 8*j + lc*2;
            s_out[row*65 + col]     = c[i][j][0];
            s_out[row*65 + col + 1] = c[i][j][1];
            s_out[(row+8)*65 + col]     = c[i][j][2];
            s_out[(row+8)*65 + col + 1] = c[i][j][3];
        }
    }
    __syncthreads();

    {
        int m = tid >> 1, g = tid & 1;
        int cbase = nt*64 + g*32;
        int s = cbase >> 8;
        int hc = cbase & 255;
        int h = hc >> 5;
        float vals[32];
#pragma unroll
        for (int d = 0; d < 32; d++) vals[d] = s_out[m*65 + g*32 + d];
        if (s == 0) {
#pragma unroll
            for (int d = 0; d < 32; d++) vals[d] += QB[hc + d];
        } else if (s == 2) {
#pragma unroll
            for (int d = 0; d < 32; d++) vals[d] += VB[hc + d];
        }
        if (s <= 1) {
            float ss = 0.f;
#pragma unroll
            for (int d = 0; d < 32; d++) ss += vals[d] * vals[d];
            float inv = 1.0f / fmaxf(sqrtf(ss), 1e-12f);
#pragma unroll
            for (int d = 0; d < 32; d++) vals[d] *= inv;
        }
        int grow = mt*128 + m;
        int win = grow >> 6, ntok = grow & 63;
        size_t idx = ((((size_t)(view*BWIN + win))*NH + h)*NTOK + ntok)*HD;
        float* dst = (s == 0) ? g_q : ((s == 1) ? g_k : g_v);
#pragma unroll
        for (int d4 = 0; d4 < 8; d4++)
            *(float4*)(dst + idx + d4*4) = *(float4*)(vals + d4*4);
    }
}

// ---------------------------------------------------------------------------
// Kernel 2: attention via mma. One block per (win, view), 512 threads.
// Scores (bf16 split mma, staged per head-pair) -> SIMT head mix -> softmax
// -> attn@V (mma) -> Y written as bf16 pair split to global for proj kernel.
// ---------------------------------------------------------------------------
// smem word-offset map
#define AT_RB    33792                 // s_attn = [512][66] fp32 before this
#define AT_QHI   (AT_RB)               // [64][20] b32 each
#define AT_QLO   (AT_RB+1280)
#define AT_KSHI  (AT_RB+2560)
#define AT_KSLO  (AT_RB+3840)
#define AT_KDHI  (AT_RB+5120)
#define AT_KDLO  (AT_RB+6400)
#define AT_SSAME (AT_RB+7680)          // [64][72] fp32
#define AT_SDIFF (AT_RB+12288)
#define AT_VTHI  (AT_RB)               // [8][32][37] b32 (overlays tiles+S)
#define AT_VTLO  (AT_RB+9472)
#define AT_SMALL (AT_RB+18944)         // pcw 128 | pcb 8 | scale 8
#define AT_WORDS (AT_SMALL+144)
#define AT_BYTES (AT_WORDS*4)

__global__ void __launch_bounds__(512, 1) attn2_kernel(
    const float* __restrict__ ls1, const float* __restrict__ pcw1, const float* __restrict__ pcb1,
    const float* __restrict__ ls2, const float* __restrict__ pcw2, const float* __restrict__ pcb2)
{
    extern __shared__ float smf[];
    uint32_t* smu = (uint32_t*)smf;
    int win = blockIdx.x, view = blockIdx.y;
    const float* LS  = view ? ls2  : ls1;
    const float* PCW = view ? pcw2 : pcw1;
    const float* PCB = view ? pcb2 : pcb1;
    int tid = threadIdx.x, wid = tid >> 5, lane = tid & 31;

    float* s_pcw   = smf + AT_SMALL;
    float* s_pcb   = smf + AT_SMALL + 128;
    float* s_scale = smf + AT_SMALL + 136;
    if (tid < 128) s_pcw[tid] = PCW[tid];
    if (tid < 8) {
        s_pcb[tid] = PCB[tid];
        s_scale[tid] = expf(fminf(LS[tid], 4.605170186f));
    }

    size_t base_same = ((size_t)(view*BWIN + win)) * NH * NTOK * HD;
    size_t base_diff = ((size_t)((view^1)*BWIN + win)) * NH * NTOK * HD;

    int m = tid & 63, nb = tid >> 6;
    float acc[8][8];
#pragma unroll
    for (int i = 0; i < 8; i++)
#pragma unroll
        for (int h = 0; h < 8; h++) acc[i][h] = 0.f;

    // score warp roles: sd (same/diff), mt (16-row n tile), nh (32-col m half)
    int sdw = wid & 1, mt = (wid >> 1) & 3, nhh = wid >> 3;
    int lg = lane >> 2, lc = lane & 3;

    for (int hp = 0; hp < 8; hp++) {
        __syncthreads();
        // stage q / k_same / k_diff tiles as bf16 hi/lo pairs [64][20]
#pragma unroll
        for (int t = 0; t < 6; t++) {
            int idx = t*512 + tid;              // 0..3071
            int tensor = idx >> 10;
            int p = idx & 1023;
            int r = p >> 4, dp = p & 15;
            const float* src = (tensor == 0) ? (g_q + base_same)
                              : ((tensor == 1) ? (g_k + base_same) : (g_k + base_diff));
            float2 v = *(const float2*)(src + hp*2048 + r*32 + dp*2);
            uint32_t hi, lo;
            split_pair(v.x, v.y, hi, lo);
            int bofs = AT_RB + tensor*2560;
            smu[bofs + r*20 + dp] = hi;
            smu[bofs + 1280 + r*20 + dp] = lo;
        }
        __syncthreads();

        // mma: C[16 n][32 m] per warp
        {
            uint32_t* qhi = smu + AT_QHI;
            uint32_t* qlo = smu + AT_QLO;
            uint32_t* khi = smu + (sdw ? AT_KDHI : AT_KSHI);
            uint32_t* klo = smu + (sdw ? AT_KDLO : AT_KSLO);
            float c[4][4];
#pragma unroll
            for (int j = 0; j < 4; j++)
#pragma unroll
                for (int r = 0; r < 4; r++) c[j][r] = 0.f;

#pragma unroll
            for (int ks = 0; ks < 2; ks++) {
                int kb = ks*8 + lc;
                int r0 = mt*16 + lg;
                uint32_t ah[4], al[4];
                ah[0] = qhi[r0*20 + kb];       ah[1] = qhi[(r0+8)*20 + kb];
                ah[2] = qhi[r0*20 + kb + 4];   ah[3] = qhi[(r0+8)*20 + kb + 4];
                al[0] = qlo[r0*20 + kb];       al[1] = qlo[(r0+8)*20 + kb];
                al[2] = qlo[r0*20 + kb + 4];   al[3] = qlo[(r0+8)*20 + kb + 4];
#pragma unroll
                for (int j = 0; j < 4; j++) {
                    int mm = nhh*32 + j*8 + lg;
                    uint32_t bh[2], bl[2];
                    bh[0] = khi[mm*20 + kb]; bh[1] = khi[mm*20 + kb + 4];
                    bl[0] = klo[mm*20 + kb]; bl[1] = klo[mm*20 + kb + 4];
                    mma_bf16(c[j], ah, bh);
                    mma_bf16(c[j], ah, bl);
                    mma_bf16(c[j], al, bh);
                }
            }
            // STS to s_same / s_diff [64][72]
            float* sS = smf + (sdw ? AT_SDIFF : AT_SSAME);
            int r0 = mt*16 + lg;
#pragma unroll
            for (int j = 0; j < 4; j++) {
                int col = nhh*32 + j*8 + lc*2;
                sS[r0*72 + col]       = c[j][0];
                sS[r0*72 + col + 1]   = c[j][1];
                sS[(r0+8)*72 + col]     = c[j][2];
                sS[(r0+8)*72 + col + 1] = c[j][3];
            }
        }
        __syncthreads();

        // SIMT head mix: acc[i][h] += w_same[h,hp]*S_same + w_diff[h,hp]*S_diff
#pragma unroll
        for (int i = 0; i < 8; i++) {
            float ssv = smf[AT_SSAME + (nb + 8*i)*72 + m];
            float sdv = smf[AT_SDIFF + (nb + 8*i)*72 + m];
#pragma unroll
            for (int h = 0; h < 8; h++)
                acc[i][h] += s_pcw[h*16 + hp]*ssv + s_pcw[h*16 + 8 + hp]*sdv;
        }
    }

    // logits -> s_attn [512][66]
    const float* gb = g_b16 + view * NH * NTOK * NTOK;
#pragma unroll
    for (int i = 0; i < 8; i++) {
        int n = nb + 8*i;
#pragma unroll
        for (int h = 0; h < 8; h++) {
            float logit = (acc[i][h] + s_pcb[h]) * s_scale[h] + gb[(h*64 + n)*64 + m];
            smf[(h*64 + n)*66 + m] = logit;
        }
    }
    __syncthreads();

    // softmax: warp per row
    for (int r = wid; r < 512; r += 16) {
        float* row = smf + r*66;
        float a = row[lane], b = row[lane + 32];
        float mx = fmaxf(a, b);
#pragma unroll
        for (int off = 16; off > 0; off >>= 1) mx = fmaxf(mx, __shfl_xor_sync(0xffffffffu, mx, off));
        float e1 = expf(a - mx), e2 = expf(b - mx);
        float s = e1 + e2;
#pragma unroll
        for (int off = 16; off > 0; off >>= 1) s += __shfl_xor_sync(0xffffffffu, s, off);
        float inv = 1.0f / s;
        row[lane] = e1 * inv;
        row[lane + 32] = e2 * inv;
    }
    __syncthreads();

    // stage V transposed bf16 pairs: vt[h][d 0..31][mpair 0..31] stride 37
#pragma unroll
    for (int t = 0; t < 4; t++) {
        int idx = t*512 + tid;               // (h, mp, dg)
        int h = idx >> 8, mp = (idx >> 3) & 31, dg = idx & 7;
        const float* vb = g_v + base_same + h*2048;
        float4 v0 = *(const float4*)(vb + (2*mp)*32 + dg*4);
        float4 v1 = *(const float4*)(vb + (2*mp + 1)*32 + dg*4);
        const float* p0 = (const float*)&v0;
        const float* p1 = (const float*)&v1;
#pragma unroll
        for (int u = 0; u < 4; u++) {
            uint32_t hi, lo;
            split_pair(p0[u], p1[u], hi, lo);
            int d = dg*4 + u;
            smu[AT_VTHI + h*1184 + d*37 + mp] = hi;
            smu[AT_VTLO + h*1184 + d*37 + mp] = lo;
        }
    }
    __syncthreads();

    // attn@V: warp = (head, 32-row n tile). C[32 n][32 d] per warp.
    {
        int h = wid >> 1, nt2 = wid & 1;
        float c2[2][4][4];
#pragma unroll
        for (int i = 0; i < 2; i++)
#pragma unroll
            for (int j = 0; j < 4; j++)
#pragma unroll
                for (int r = 0; r < 4; r++) c2[i][j][r] = 0.f;

        const float* srow = smf + (h*64 + nt2*32)*66;
#pragma unroll
        for (int kc = 0; kc < 4; kc++) {
            uint32_t ah[2][4], al[2][4];
#pragma unroll
            for (int i = 0; i < 2; i++) {
                int r = i*16 + lg;
                int k = kc*16 + lc*2;
#pragma unroll
                for (int u = 0; u < 4; u++) {
                    int rr = r + (u & 1)*8;
                    int kk = k + (u >> 1)*8;
                    float x0 = srow[rr*66 + kk];
                    float x1 = srow[rr*66 + kk + 1];
                    split_pair(x0, x1, ah[i][u], al[i][u]);
                }
            }
#pragma unroll
            for (int j = 0; j < 4; j++) {
                int d = j*8 + lg;
                int mpb = kc*8 + lc;
                uint32_t bh[2], bl[2];
                bh[0] = smu[AT_VTHI + h*1184 + d*37 + mpb];
                bh[1] = smu[AT_VTHI + h*1184 + d*37 + mpb + 4];
                bl[0] = smu[AT_VTLO + h*1184 + d*37 + mpb];
                bl[1] = smu[AT_VTLO + h*1184 + d*37 + mpb + 4];
#pragma unroll
                for (int i = 0; i < 2; i++) {
                    mma_bf16(c2[i][j], ah[i], bh);
                    mma_bf16(c2[i][j], ah[i], bl);
                    mma_bf16(c2[i][j], al[i], bh);
                }
            }
        }

        // write Y as bf16 pair split to global (pairs along channel)
        uint32_t yrow0 = ((uint32_t)(view*BWIN + win))*64u;
#pragma unroll
        for (int i = 0; i < 2; i++) {
            int n0 = nt2*32 + i*16 + lg;
#pragma unroll
            for (int j = 0; j < 4; j++) {
                int pidx = h*16 + j*4 + lc;
                uint32_t hi, lo;
                split_pair(c2[i][j][0], c2[i][j][1], hi, lo);
                g_yhi[(yrow0 + n0)*128u + pidx] = hi;
                g_ylo[(yrow0 + n0)*128u + pidx] = lo;
                split_pair(c2[i][j][2], c2[i][j][3], hi, lo);
                g_yhi[(yrow0 + n0 + 8)*128u + pidx] = hi;
                g_ylo[(yrow0 + n0 + 8)*128u + pidx] = lo;
            }
        }
    }
}

// ---------------------------------------------------------------------------
// Kernel 3: proj GEMM: out = Y @ PW^T + PB. Clone of qkv_mma structure.
// ---------------------------------------------------------------------------
__global__ void __launch_bounds__(256, 1) proj_mma_kernel(
    const float* __restrict__ pb1, const float* __restrict__ pb2,
    float* __restrict__ out)
{
    extern __shared__ uint32_t smu[];
    uint32_t* sA_hi = smu;           // [128][20]
    uint32_t* sA_lo = smu + 2560;
    uint32_t* sB_hi = smu + 5120;    // [64][20]
    uint32_t* sB_lo = smu + 6400;

    int tid = threadIdx.x;
    int wid = tid >> 5, lane = tid & 31;
    int warp_m = wid & 3, warp_n = wid >> 2;
    int nt = blockIdx.x;      // 0..3
    int mt = blockIdx.y;      // 0..255
    int view = blockIdx.z;

    const float* PB = view ? pb2 : pb1;

    float c[2][4][4];
#pragma unroll
    for (int i = 0; i < 2; i++)
#pragma unroll
        for (int j = 0; j < 4; j++)
#pragma unroll
            for (int r = 0; r < 4; r++) c[i][j][r] = 0.f;

    uint32_t arow0 = (uint32_t)(view*32768 + mt*128);
    uint32_t brow0 = (uint32_t)(view*256 + nt*64);

    int lg = lane >> 2;
    int lc = lane & 3;

    for (int kc = 0; kc < 8; kc++) {
        __syncthreads();
#pragma unroll
        for (int t = 0; t < 2; t++) {
            int idx = t*256 + tid;
            int row = idx >> 2, cc = (idx & 3) * 4;
            uint32_t gofs = (arow0 + row)*128u + kc*16 + cc;
            *(uint4*)(sA_hi + row*20 + cc) = *(const uint4*)(g_yhi + gofs);
            *(uint4*)(sA_lo + row*20 + cc) = *(const uint4*)(g_ylo + gofs);
        }
        {
            int row = tid >> 2, cc = (tid & 3) * 4;
            uint32_t gofs = (brow0 + row)*128u + kc*16 + cc;
            *(uint4*)(sB_hi + row*20 + cc) = *(const uint4*)(g_pwhi + gofs);
            *(uint4*)(sB_lo + row*20 + cc) = *(const uint4*)(g_pwlo + gofs);
        }
        __syncthreads();

#pragma unroll
        for (int ks = 0; ks < 2; ks++) {
            uint32_t ah[2][4], al[2][4], bh[4][2], bl[4][2];
#pragma unroll
            for (int i = 0; i < 2; i++) {
                int r0 = warp_m*32 + 16*i + lg;
                int kb = ks*8 + lc;
                ah[i][0] = sA_hi[r0*20 + kb];
                ah[i][1] = sA_hi[(r0+8)*20 + kb];
                ah[i][2] = sA_hi[r0*20 + kb + 4];
                ah[i][3] = sA_hi[(r0+8)*20 + kb + 4];
                al[i][0] = sA_lo[r0*20 + kb];
                al[i][1] = sA_lo[(r0+8)*20 + kb];
                al[i][2] = sA_lo[r0*20 + kb + 4];
                al[i][3] = sA_lo[(r0+8)*20 + kb + 4];
            }
#pragma unroll
            for (int j = 0; j < 4; j++) {
                int n = warp_n*32 + 8*j + lg;
                int kb = ks*8 + lc;
                bh[j][0] = sB_hi[n*20 + kb];
                bh[j][1] = sB_hi[n*20 + kb + 4];
                bl[j][0] = sB_lo[n*20 + kb];
                bl[j][1] = sB_lo[n*20 + kb + 4];
            }
#pragma unroll
            for (int i = 0; i < 2; i++)
#pragma unroll
                for (int j = 0; j < 4; j++) {
                    mma_bf16(c[i][j], ah[i], bh[j]);
                    mma_bf16(c[i][j], ah[i], bl[j]);
                    mma_bf16(c[i][j], al[i], bh[j]);
                }
        }
    }
    __syncthreads();

    float* s_out = (float*)smu;
#pragma unroll
    for (int i = 0; i < 2; i++) {
        int row = warp_m*32 + 16*i + lg;
#pragma unroll
        for (int j = 0; j < 4; j++) {
            int col = warp_n*32 + 8*j + lc*2;
            s_out[row*65 + col]     = c[i][j][0];
            s_out[row*65 + col + 1] = c[i][j][1];
            s_out[(row+8)*65 + col]     = c[i][j][2];
            s_out[(row+8)*65 + col + 1] = c[i][j][3];
        }
    }
    __syncthreads();

    for (int i = tid; i < 8192; i += 256) {
        int mm = i >> 6, j = i & 63;
        int grow = mt*128 + mm;
        out[((size_t)view*32768 + grow)*256 + nt*64 + j] = s_out[mm*65 + j] + PB[nt*64 + j];
    }
}

// ---------------------------------------------------------------------------
extern "C" void kernel_launch(void* const* d_in, const int* in_sizes, int n_in,
                              void* d_out, int out_size)
{
    const float* x1   = (const float*)d_in[0];
    const float* x2   = (const float*)d_in[1];
    const float* qkvw1 = (const float*)d_in[2];
    const float* qb1  = (const float*)d_in[3];
    const float* vb1  = (const float*)d_in[4];
    const float* pw1  = (const float*)d_in[5];
    const float* pb1  = (const float*)d_in[6];
    const float* ls1  = (const float*)d_in[7];
    const float* c1w1 = (const float*)d_in[8];
    const float* c1b1 = (const float*)d_in[9];
    const float* c1w2 = (const float*)d_in[10];
    const float* pcw1 = (const float*)d_in[11];
    const float* pcb1 = (const float*)d_in[12];
    const float* qkvw2 = (const float*)d_in[13];
    const float* qb2  = (const float*)d_in[14];
    const float* vb2  = (const float*)d_in[15];
    const float* pw2  = (const float*)d_in[16];
    const float* pb2  = (const float*)d_in[17];
    const float* ls2  = (const float*)d_in[18];
    const float* c2w1 = (const float*)d_in[19];
    const float* c2b1 = (const float*)d_in[20];
    const float* c2w2 = (const float*)d_in[21];
    const float* pcw2 = (const float*)d_in[22];
    const float* pcb2 = (const float*)d_in[23];
    float* out = (float*)d_out;

    cpb_kernel<<<2, 256>>>(c1w1, c1b1, c1w2, c2w1, c2b1, c2w2);

    {
        uint32_t total = XPAIRS + WPAIRS + PWPAIRS;
        prep_kernel<<<(total + 255) / 256, 256>>>(x1, x2, qkvw1, qkvw2, pw1, pw2);
    }

    cudaFuncSetAttribute(qkv_mma_kernel, cudaFuncAttributeMaxDynamicSharedMemorySize, QSM_BYTES);
    qkv_mma_kernel<<<dim3(12, 256, 2), 256, QSM_BYTES>>>(qb1, vb1, qb2, vb2);

    cudaFuncSetAttribute(attn2_kernel, cudaFuncAttributeMaxDynamicSharedMemorySize, AT_BYTES);
    attn2_kernel<<<dim3(512, 2), 512, AT_BYTES>>>(ls1, pcw1, pcb1, ls2, pcw2, pcb2);

    cudaFuncSetAttribute(proj_mma_kernel, cudaFuncAttributeMaxDynamicSharedMemorySize, QSM_BYTES);
    proj_mma_kernel<<<dim3(4, 256, 2), 256, QSM_BYTES>>>(pb1, pb2, out);
}